// round 1
// baseline (speedup 1.0000x reference)
#include <cuda_runtime.h>

// Problem dims (InnerAttention): x[B,M,D], y[B,N,D] -> out[B,N,D]
// S[b,m,n] = <x[b,m,:], y[b,n,:]>, P = softmax over n, out[b,n,d] = sum_m P[b,m,n]*x[b,m,d]
#define BATCH 8
#define MDIM  2048
#define NDIM  2048
#define DDIM  1024

// 128 MB scratch for S / P (device global — allocation-free per harness rules)
__device__ float g_P[(size_t)BATCH * MDIM * NDIM];

// ---------------------------------------------------------------------------
// GEMM1 (NT): C[M,N] = A[M,K] * B[N,K]^T   (both K-contiguous, row-major)
// 128x128 CTA tile, BK=8, 256 threads, 8x8 per-thread micro-tile.
// ---------------------------------------------------------------------------
__global__ __launch_bounds__(256, 2)
void gemm_nt_kernel(const float* __restrict__ A, const float* __restrict__ B,
                    float* __restrict__ C, int M, int N, int K)
{
    const int BM = 128, BN = 128, BK = 8;
    __shared__ float As[BK][BM];
    __shared__ float Bs[BK][BN];

    const int b = blockIdx.z;
    const float* Ab = A + (size_t)b * M * K + (size_t)blockIdx.y * BM * K;
    const float* Bb = B + (size_t)b * N * K + (size_t)blockIdx.x * BN * K;
    float*       Cb = C + (size_t)b * M * N + (size_t)blockIdx.y * BM * N + (size_t)blockIdx.x * BN;

    const int tid = threadIdx.x;          // 0..255
    const int a_row = tid >> 1;           // 0..127
    const int a_col = (tid & 1) * 4;      // 0 or 4
    const int m_base = (tid >> 4) * 8;    // 0..120
    const int n_base = (tid & 15) * 8;    // 0..120

    float acc[8][8];
    #pragma unroll
    for (int i = 0; i < 8; i++)
        #pragma unroll
        for (int j = 0; j < 8; j++) acc[i][j] = 0.f;

    for (int k0 = 0; k0 < K; k0 += BK) {
        float4 av = *(const float4*)(Ab + (size_t)a_row * K + k0 + a_col);
        float4 bv = *(const float4*)(Bb + (size_t)a_row * K + k0 + a_col);
        // transpose into k-major smem
        As[a_col + 0][a_row] = av.x; As[a_col + 1][a_row] = av.y;
        As[a_col + 2][a_row] = av.z; As[a_col + 3][a_row] = av.w;
        Bs[a_col + 0][a_row] = bv.x; Bs[a_col + 1][a_row] = bv.y;
        Bs[a_col + 2][a_row] = bv.z; Bs[a_col + 3][a_row] = bv.w;
        __syncthreads();

        #pragma unroll
        for (int k = 0; k < BK; k++) {
            float ar[8], br[8];
            float4 a0 = *(const float4*)&As[k][m_base];
            float4 a1 = *(const float4*)&As[k][m_base + 4];
            float4 b0 = *(const float4*)&Bs[k][n_base];
            float4 b1 = *(const float4*)&Bs[k][n_base + 4];
            ar[0]=a0.x; ar[1]=a0.y; ar[2]=a0.z; ar[3]=a0.w;
            ar[4]=a1.x; ar[5]=a1.y; ar[6]=a1.z; ar[7]=a1.w;
            br[0]=b0.x; br[1]=b0.y; br[2]=b0.z; br[3]=b0.w;
            br[4]=b1.x; br[5]=b1.y; br[6]=b1.z; br[7]=b1.w;
            #pragma unroll
            for (int i = 0; i < 8; i++)
                #pragma unroll
                for (int j = 0; j < 8; j++)
                    acc[i][j] = fmaf(ar[i], br[j], acc[i][j]);
        }
        __syncthreads();
    }

    #pragma unroll
    for (int i = 0; i < 8; i++) {
        float4 c0 = {acc[i][0], acc[i][1], acc[i][2], acc[i][3]};
        float4 c1 = {acc[i][4], acc[i][5], acc[i][6], acc[i][7]};
        *(float4*)(Cb + (size_t)(m_base + i) * N + n_base)     = c0;
        *(float4*)(Cb + (size_t)(m_base + i) * N + n_base + 4) = c1;
    }
}

// ---------------------------------------------------------------------------
// Row softmax in place: one CTA per row of length NDIM (=2048), 256 threads.
// ---------------------------------------------------------------------------
__global__ __launch_bounds__(256)
void softmax_rows_kernel(float* __restrict__ P)
{
    float* p = P + (size_t)blockIdx.x * NDIM;
    const int tid = threadIdx.x;
    const int lane = tid & 31;
    const int wid  = tid >> 5;
    __shared__ float red[8];

    // 2048 = 256 threads * 8 floats: two coalesced float4 chunks
    float4 v0 = *(const float4*)(p + tid * 4);
    float4 v1 = *(const float4*)(p + 1024 + tid * 4);

    float m = fmaxf(fmaxf(fmaxf(v0.x, v0.y), fmaxf(v0.z, v0.w)),
                    fmaxf(fmaxf(v1.x, v1.y), fmaxf(v1.z, v1.w)));
    #pragma unroll
    for (int off = 16; off > 0; off >>= 1)
        m = fmaxf(m, __shfl_xor_sync(0xffffffffu, m, off));
    if (lane == 0) red[wid] = m;
    __syncthreads();
    if (tid == 0) {
        float mm = red[0];
        #pragma unroll
        for (int w = 1; w < 8; w++) mm = fmaxf(mm, red[w]);
        red[0] = mm;
    }
    __syncthreads();
    const float rowmax = red[0];
    __syncthreads();

    v0.x = __expf(v0.x - rowmax); v0.y = __expf(v0.y - rowmax);
    v0.z = __expf(v0.z - rowmax); v0.w = __expf(v0.w - rowmax);
    v1.x = __expf(v1.x - rowmax); v1.y = __expf(v1.y - rowmax);
    v1.z = __expf(v1.z - rowmax); v1.w = __expf(v1.w - rowmax);

    float s = v0.x + v0.y + v0.z + v0.w + v1.x + v1.y + v1.z + v1.w;
    #pragma unroll
    for (int off = 16; off > 0; off >>= 1)
        s += __shfl_xor_sync(0xffffffffu, s, off);
    if (lane == 0) red[wid] = s;
    __syncthreads();
    if (tid == 0) {
        float ss = red[0];
        #pragma unroll
        for (int w = 1; w < 8; w++) ss += red[w];
        red[0] = ss;
    }
    __syncthreads();
    const float scale = 1.0f / red[0];

    v0.x *= scale; v0.y *= scale; v0.z *= scale; v0.w *= scale;
    v1.x *= scale; v1.y *= scale; v1.z *= scale; v1.w *= scale;
    *(float4*)(p + tid * 4) = v0;
    *(float4*)(p + 1024 + tid * 4) = v1;
}

// ---------------------------------------------------------------------------
// GEMM2 (TN): O[N,D] = P^T * X, with P stored [K=M, N], X stored [K=M, D].
// Both smem tiles load naturally in [K][MN] layout (coalesced, no transpose).
// ---------------------------------------------------------------------------
__global__ __launch_bounds__(256, 2)
void gemm_tn_kernel(const float* __restrict__ P, const float* __restrict__ X,
                    float* __restrict__ O, int N, int D, int K)
{
    const int BN = 128, BD = 128, BK = 8;
    __shared__ float Ps[BK][BN];
    __shared__ float Xs[BK][BD];

    const int b = blockIdx.z;
    const float* Pb = P + (size_t)b * K * N + (size_t)blockIdx.y * BN;
    const float* Xb = X + (size_t)b * K * D + (size_t)blockIdx.x * BD;
    float*       Ob = O + (size_t)b * N * D + (size_t)blockIdx.y * BN * D + (size_t)blockIdx.x * BD;

    const int tid = threadIdx.x;
    const int kr  = tid >> 5;          // 0..7
    const int col = (tid & 31) * 4;    // 0..124
    const int n_base = (tid >> 4) * 8;
    const int d_base = (tid & 15) * 8;

    float acc[8][8];
    #pragma unroll
    for (int i = 0; i < 8; i++)
        #pragma unroll
        for (int j = 0; j < 8; j++) acc[i][j] = 0.f;

    for (int k0 = 0; k0 < K; k0 += BK) {
        *(float4*)&Ps[kr][col] = *(const float4*)(Pb + (size_t)(k0 + kr) * N + col);
        *(float4*)&Xs[kr][col] = *(const float4*)(Xb + (size_t)(k0 + kr) * D + col);
        __syncthreads();

        #pragma unroll
        for (int k = 0; k < BK; k++) {
            float ar[8], br[8];
            float4 a0 = *(const float4*)&Ps[k][n_base];
            float4 a1 = *(const float4*)&Ps[k][n_base + 4];
            float4 b0 = *(const float4*)&Xs[k][d_base];
            float4 b1 = *(const float4*)&Xs[k][d_base + 4];
            ar[0]=a0.x; ar[1]=a0.y; ar[2]=a0.z; ar[3]=a0.w;
            ar[4]=a1.x; ar[5]=a1.y; ar[6]=a1.z; ar[7]=a1.w;
            br[0]=b0.x; br[1]=b0.y; br[2]=b0.z; br[3]=b0.w;
            br[4]=b1.x; br[5]=b1.y; br[6]=b1.z; br[7]=b1.w;
            #pragma unroll
            for (int i = 0; i < 8; i++)
                #pragma unroll
                for (int j = 0; j < 8; j++)
                    acc[i][j] = fmaf(ar[i], br[j], acc[i][j]);
        }
        __syncthreads();
    }

    #pragma unroll
    for (int i = 0; i < 8; i++) {
        float4 c0 = {acc[i][0], acc[i][1], acc[i][2], acc[i][3]};
        float4 c1 = {acc[i][4], acc[i][5], acc[i][6], acc[i][7]};
        *(float4*)(Ob + (size_t)(n_base + i) * D + d_base)     = c0;
        *(float4*)(Ob + (size_t)(n_base + i) * D + d_base + 4) = c1;
    }
}

// ---------------------------------------------------------------------------
extern "C" void kernel_launch(void* const* d_in, const int* in_sizes, int n_in,
                              void* d_out, int out_size)
{
    const float* x = (const float*)d_in[0];   // [B, M, D]
    const float* y = (const float*)d_in[1];   // [B, N, D]
    float* out = (float*)d_out;               // [B, N, D]

    float* Pg = nullptr;
    cudaGetSymbolAddress((void**)&Pg, g_P);

    // GEMM1: S[b] = X[b] * Y[b]^T  -> g_P
    {
        dim3 grid(NDIM / 128, MDIM / 128, BATCH);
        gemm_nt_kernel<<<grid, 256>>>(x, y, Pg, MDIM, NDIM, DDIM);
    }
    // Softmax rows of S in place -> P
    {
        softmax_rows_kernel<<<BATCH * MDIM, 256>>>(Pg);
    }
    // GEMM2: O[b] = P[b]^T * X[b]
    {
        dim3 grid(DDIM / 128, NDIM / 128, BATCH);
        gemm_tn_kernel<<<grid, 256>>>(Pg, x, out, NDIM, DDIM, MDIM);
    }
}